// round 12
// baseline (speedup 1.0000x reference)
#include <cuda_runtime.h>
#include <cuda_bf16.h>
#include <cstdint>

#define NC 256
#define KK 16
#define DD 256
#define NN 4096
#define MARGINF 1.0f
#define EPSF 1e-6f

#define TI 128
#define TJ 128
#define KC 64            // bf16 per k-chunk (128B rows)
#define NCHUNK 4         // K = 256 (hi-only)
#define NTI (NN / TI)    // 32
#define NTILES (NTI * (NTI + 1) / 2)   // 528
#define GRID 296         // persistent: 2 CTAs/SM, all resident

#define STAGE_BYTES (TI*128 + TJ*128)   // 32 KB
#define SQ_OFF      (3 * STAGE_BYTES)   // 96 KB
#define DYN_SMEM    (SQ_OFF + 1024)

typedef unsigned long long u64;

__device__ __nv_bfloat16 g_panel[(size_t)NN * 256];   // hi only
__device__ float g_sq[NN];
__device__ float g_sum[NN];         // row sums (for eps correction)
__device__ u64   g_neg_pack[NN];    // (d2_bits<<32)|j   : atomicMin
__device__ u64   g_pos_pack[NN];    // (d2_bits<<32)|~j  : atomicMax
__device__ unsigned int g_done;

#define LDSM4(r, a) \
    asm volatile("ldmatrix.sync.aligned.m8n8.x4.shared.b16 {%0,%1,%2,%3}, [%4];" \
        : "=r"((r)[0]), "=r"((r)[1]), "=r"((r)[2]), "=r"((r)[3]) : "r"(a))

#define MMA16816(c, a, b) \
    asm volatile("mma.sync.aligned.m16n8k16.row.col.f32.bf16.bf16.f32 " \
        "{%0,%1,%2,%3}, {%4,%5,%6,%7}, {%8,%9}, {%0,%1,%2,%3};" \
        : "+f"((c)[0]), "+f"((c)[1]), "+f"((c)[2]), "+f"((c)[3]) \
        : "r"((a)[0]), "r"((a)[1]), "r"((a)[2]), "r"((a)[3]), \
          "r"((b)[0]), "r"((b)[1]))

__device__ __forceinline__ void cp16(uint32_t dst, const void* src) {
    asm volatile("cp.async.cg.shared.global [%0], [%1], 16;" :: "r"(dst), "l"(src));
}
#define CP_COMMIT() asm volatile("cp.async.commit_group;")
#define CP_WAIT(n)  asm volatile("cp.async.wait_group %0;" :: "n"(n))

// ---------------- prep: fp32 -> bf16 hi panel + sq + sum + init ----------------
__global__ __launch_bounds__(256) void prep_kernel(const float* __restrict__ emb) {
    if (blockIdx.x == 0 && threadIdx.x == 0) g_done = 0u;

    const int row  = blockIdx.x * 8 + (threadIdx.x >> 5);
    const int lane = threadIdx.x & 31;

    const float4* src = (const float4*)(emb + (size_t)row * DD);
    float4 a = __ldg(&src[lane * 2]);
    float4 b = __ldg(&src[lane * 2 + 1]);
    float x[8] = {a.x, a.y, a.z, a.w, b.x, b.y, b.z, b.w};

    alignas(16) __nv_bfloat16 hi[8];
    float s = 0.f, m = 0.f;
    #pragma unroll
    for (int t = 0; t < 8; t++) {
        hi[t] = __float2bfloat16(x[t]);
        s += x[t] * x[t];
        m += x[t];
    }
    *(uint4*)(g_panel + (size_t)row * 256 + lane * 8) = *(const uint4*)hi;

    #pragma unroll
    for (int off = 16; off; off >>= 1) {
        s += __shfl_xor_sync(0xffffffffu, s, off);
        m += __shfl_xor_sync(0xffffffffu, m, off);
    }
    if (lane == 0) {
        g_sq[row]  = s;
        g_sum[row] = m;
        g_neg_pack[row] = 0xffffffffffffffffull;
        g_pos_pack[row] = 0ull;
    }
}

__device__ __forceinline__ u64 pack_min(float v, int j) {
    return ((u64)__float_as_uint(fmaxf(v, 0.f)) << 32) | (unsigned)j;
}
__device__ __forceinline__ u64 pack_max(float v, int j) {
    return ((u64)__float_as_uint(fmaxf(v, 0.f)) << 32) | (unsigned)(~j);
}

// ---------------- persistent triangular GEMM + atomic epilogue + fused loss ----------------
__global__ __launch_bounds__(256, 2)
void gemm_kernel(float* __restrict__ out) {
    extern __shared__ char dsm[];
    __shared__ int s_last;
    const int tid = threadIdx.x;
    const int wid = tid >> 5, lane = tid & 31;
    const int wm  = wid >> 2, wn = wid & 3;   // 2 x 4 warp grid

    const uint32_t sbase = (uint32_t)__cvta_generic_to_shared(dsm);
    float* s_sqi = (float*)(dsm + SQ_OFF);
    float* s_sqj = (float*)(dsm + SQ_OFF + 512);

    const char* gp = (const char*)g_panel;

    auto decode = [](int t, int& ti, int& tj) {
        int rem = t, a = 0;
        while (rem >= NTI - a) { rem -= NTI - a; a++; }
        ti = a; tj = a + rem;
    };

    auto load_stage = [&](int i0, int j0, int kc, int s) {
        const uint32_t aBase = sbase + s * STAGE_BYTES;
        const uint32_t bBase = aBase + TI * 128;
        const int koff = kc * KC;
        #pragma unroll
        for (int it = 0; it < 4; it++) {
            const int idx = tid + 256 * it;
            const int row = idx >> 3, seg = idx & 7;
            const int off = row * 128 + seg * 16;
            cp16(aBase + (off ^ ((off >> 3) & 0x70)),
                 gp + ((size_t)(i0 + row) * 256 + koff + seg * 8) * 2);
        }
        #pragma unroll
        for (int it = 0; it < 4; it++) {
            const int idx = tid + 256 * it;
            const int row = idx >> 3, seg = idx & 7;
            const int off = row * 128 + seg * 16;
            cp16(bBase + (off ^ ((off >> 3) & 0x70)),
                 gp + ((size_t)(j0 + row) * 256 + koff + seg * 8) * 2);
        }
        CP_COMMIT();
    };

    int t = blockIdx.x;
    int ti, tj; decode(t, ti, tj);
    int i0 = ti * TI, j0 = tj * TJ;
    int b = 0;                        // stage base for current tile (advances +1 mod 3 per tile)

    load_stage(i0, j0, 0, 0);
    load_stage(i0, j0, 1, 1);

    while (true) {
        int tn = t + GRID;
        const bool lastTile = (tn >= NTILES);
        int tin = ti, tjn = tj;
        if (!lastTile) decode(tn, tin, tjn);
        const int i0n = tin * TI, j0n = tjn * TJ;
        const bool diag = (ti == tj);

        if (tid < 128) s_sqi[tid] = g_sq[i0 + tid];
        else           s_sqj[tid - 128] = g_sq[j0 + tid - 128];

        float acc[4][4][4];
        #pragma unroll
        for (int a = 0; a < 4; a++)
            #pragma unroll
            for (int c = 0; c < 4; c++)
                #pragma unroll
                for (int e = 0; e < 4; e++) acc[a][c][e] = 0.f;

        #pragma unroll
        for (int kc = 0; kc < NCHUNK; kc++) {
            if (lastTile && kc == NCHUNK - 1) { CP_WAIT(0); }
            else                              { CP_WAIT(1); }
            __syncthreads();   // all warps done with chunk kc-1; stage (b+kc+2)%3 free

            if (kc < 2)            load_stage(i0, j0, kc + 2, (b + kc + 2) % 3);
            else if (!lastTile)    load_stage(i0n, j0n, kc - 2, (b + kc + 2) % 3);

            const uint32_t aBase = sbase + ((b + kc) % 3) * STAGE_BYTES;
            const uint32_t bBase = aBase + TI * 128;

            #pragma unroll
            for (int ks = 0; ks < 4; ks++) {
                uint32_t afr[4][4];
                #pragma unroll
                for (int fm = 0; fm < 4; fm++) {
                    const int row = wm * 64 + fm * 16 + (lane & 15);
                    const int ch  = (ks * 2 + (lane >> 4)) ^ (row & 7);
                    LDSM4(afr[fm], aBase + row * 128 + ch * 16);
                }
                uint32_t bfr[2][4];
                #pragma unroll
                for (int g = 0; g < 2; g++) {
                    const int row = wn * 32 + g * 16 + (lane & 7) + ((lane >> 4) & 1) * 8;
                    const int ch  = (ks * 2 + ((lane >> 3) & 1)) ^ (row & 7);
                    LDSM4(bfr[g], bBase + row * 128 + ch * 16);
                }
                #pragma unroll
                for (int fm = 0; fm < 4; fm++)
                    #pragma unroll
                    for (int fn = 0; fn < 4; fn++)
                        MMA16816(acc[fm][fn], afr[fm], &bfr[fn >> 1][(fn & 1) * 2]);
            }
        }

        // ---- epilogue: packed atomics ----
        #pragma unroll
        for (int fm = 0; fm < 4; fm++) {
            #pragma unroll
            for (int h = 0; h < 2; h++) {
                const int rl = wm * 64 + fm * 16 + h * 8 + (lane >> 2);
                const int i  = i0 + rl;
                const int ci = i >> 4;
                const float sqi = s_sqi[rl];

                float bnv = 3.0e38f;  int bnj = 0x7fffffff;
                float bpv = -3.0e38f; int bpj = 0;

                #pragma unroll
                for (int fn = 0; fn < 4; fn++) {
                    #pragma unroll
                    for (int e = 0; e < 2; e++) {
                        const int cl = wn * 32 + fn * 8 + (lane & 3) * 2 + e;
                        const int j  = j0 + cl;
                        const float d2 = sqi + s_sqj[cl] - 2.f * acc[fm][fn][h * 2 + e];
                        if (diag && ((j >> 4) == ci)) {
                            if (d2 > bpv) { bpv = d2; bpj = j; }
                        } else {
                            if (d2 < bnv) { bnv = d2; bnj = j; }
                        }
                    }
                }
                #pragma unroll
                for (int m = 1; m <= 2; m <<= 1) {
                    float ov; int oj;
                    ov = __shfl_xor_sync(0xffffffffu, bnv, m);
                    oj = __shfl_xor_sync(0xffffffffu, bnj, m);
                    if (ov < bnv || (ov == bnv && oj < bnj)) { bnv = ov; bnj = oj; }
                    ov = __shfl_xor_sync(0xffffffffu, bpv, m);
                    oj = __shfl_xor_sync(0xffffffffu, bpj, m);
                    if (ov > bpv || (ov == bpv && oj < bpj)) { bpv = ov; bpj = oj; }
                }
                if ((lane & 3) == 0) {
                    atomicMin(&g_neg_pack[i], pack_min(bnv, bnj));
                    if (diag) atomicMax(&g_pos_pack[i], pack_max(bpv, bpj));
                }
            }
        }

        if (!diag) {
            #pragma unroll
            for (int fn = 0; fn < 4; fn++) {
                #pragma unroll
                for (int e = 0; e < 2; e++) {
                    const int cl = wn * 32 + fn * 8 + (lane & 3) * 2 + e;
                    const float sqj = s_sqj[cl];
                    float bv = 3.0e38f; int bi = 0x7fffffff;
                    #pragma unroll
                    for (int fm = 0; fm < 4; fm++) {
                        #pragma unroll
                        for (int h = 0; h < 2; h++) {
                            const int rl = wm * 64 + fm * 16 + h * 8 + (lane >> 2);
                            const float d2 = s_sqi[rl] + sqj - 2.f * acc[fm][fn][h * 2 + e];
                            if (d2 < bv) { bv = d2; bi = i0 + rl; }
                        }
                    }
                    #pragma unroll
                    for (int m = 4; m <= 16; m <<= 1) {
                        const float ov = __shfl_xor_sync(0xffffffffu, bv, m);
                        const int   oi = __shfl_xor_sync(0xffffffffu, bi, m);
                        if (ov < bv || (ov == bv && oi < bi)) { bv = ov; bi = oi; }
                    }
                    if ((lane >> 2) == 0)
                        atomicMin(&g_neg_pack[j0 + cl], pack_min(bv, bi));
                }
            }
        }

        __syncthreads();   // protect s_sq / stage reuse for next tile
        if (lastTile) break;
        t = tn; ti = tin; tj = tjn; i0 = i0n; j0 = j0n;
        b = (b + 1) % 3;
    }

    // ---- fused finalize: last CTA computes the loss from packs ----
    __threadfence();
    __syncthreads();
    if (tid == 0) s_last = (atomicAdd(&g_done, 1u) == GRID - 1) ? 1 : 0;
    __syncthreads();

    if (s_last) {
        __threadfence();
        float* sh = (float*)dsm;
        const float eterm = (float)DD * EPSF * EPSF;
        float lsum = 0.f;
        #pragma unroll
        for (int r = 0; r < NN / 256; r++) {
            const int i = r * 256 + tid;
            const u64 np = g_neg_pack[i];
            const u64 pp = g_pos_pack[i];
            const int n = (int)(unsigned)(np & 0xffffffffull);
            const int p = (int)~(unsigned)(pp & 0xffffffffull);
            const float d2n = __uint_as_float((unsigned)(np >> 32));
            const float d2p = __uint_as_float((unsigned)(pp >> 32));
            const float Si = g_sum[i];
            const float ap2 = d2p + 2.f * EPSF * (Si - g_sum[p]) + eterm;
            const float an2 = d2n + 2.f * EPSF * (Si - g_sum[n]) + eterm;
            lsum += fmaxf(sqrtf(fmaxf(ap2, 0.f)) - sqrtf(fmaxf(an2, 0.f)) + MARGINF, 0.f);
        }
        sh[tid] = lsum;
        __syncthreads();
        for (int off = 128; off; off >>= 1) {
            if (tid < off) sh[tid] += sh[tid + off];
            __syncthreads();
        }
        if (tid == 0) out[0] = sh[0] * (1.0f / (float)NN);
    }
}

extern "C" void kernel_launch(void* const* d_in, const int* in_sizes, int n_in,
                              void* d_out, int out_size) {
    const float* emb = (const float*)d_in[0];
    float* out = (float*)d_out;

    static bool attr_set = false;
    if (!attr_set) {
        cudaFuncSetAttribute(gemm_kernel, cudaFuncAttributeMaxDynamicSharedMemorySize, DYN_SMEM);
        attr_set = true;
    }

    prep_kernel<<<NN / 8, 256>>>(emb);
    gemm_kernel<<<GRID, 256, DYN_SMEM>>>(out);
}

// round 13
// speedup vs baseline: 1.4513x; 1.4513x over previous
#include <cuda_runtime.h>
#include <cuda_bf16.h>
#include <cstdint>

#define NC 256
#define KK 16
#define DD 256
#define NN 4096
#define MARGINF 1.0f
#define EPSF 1e-6f

#define TI 128
#define TJ 128
#define KC 64            // bf16 per k-chunk (128B rows)
#define NCHUNK 4         // K = 256 (hi-only)
#define NTI (NN / TI)    // 32
#define NTILES (NTI * (NTI + 1) / 2)   // 528

#define STAGE_BYTES (TI*128 + TJ*128)   // 32 KB
#define SQ_OFF      (3 * STAGE_BYTES)   // 96 KB
#define DYN_SMEM    (SQ_OFF + 1024)

typedef unsigned long long u64;

__device__ __nv_bfloat16 g_panel[(size_t)NN * 256];   // hi only
__device__ float g_sq[NN];
__device__ float g_sum[NN];         // row sums (for eps correction)
__device__ u64   g_neg_pack[NN];    // (d2_bits<<32)|j   : atomicMin
__device__ u64   g_pos_pack[NN];    // (d2_bits<<32)|~j  : atomicMax
__device__ unsigned int g_done;

#define LDSM4(r, a) \
    asm volatile("ldmatrix.sync.aligned.m8n8.x4.shared.b16 {%0,%1,%2,%3}, [%4];" \
        : "=r"((r)[0]), "=r"((r)[1]), "=r"((r)[2]), "=r"((r)[3]) : "r"(a))

#define MMA16816(c, a, b) \
    asm volatile("mma.sync.aligned.m16n8k16.row.col.f32.bf16.bf16.f32 " \
        "{%0,%1,%2,%3}, {%4,%5,%6,%7}, {%8,%9}, {%0,%1,%2,%3};" \
        : "+f"((c)[0]), "+f"((c)[1]), "+f"((c)[2]), "+f"((c)[3]) \
        : "r"((a)[0]), "r"((a)[1]), "r"((a)[2]), "r"((a)[3]), \
          "r"((b)[0]), "r"((b)[1]))

__device__ __forceinline__ void cp16(uint32_t dst, const void* src) {
    asm volatile("cp.async.cg.shared.global [%0], [%1], 16;" :: "r"(dst), "l"(src));
}
#define CP_COMMIT() asm volatile("cp.async.commit_group;")
#define CP_WAIT(n)  asm volatile("cp.async.wait_group %0;" :: "n"(n))

// ---------------- prep: fp32 -> bf16 panel + sq/sum, 2 rows/warp for MLP ----------------
__global__ __launch_bounds__(256) void prep_kernel(const float* __restrict__ emb) {
    if (blockIdx.x == 0 && threadIdx.x == 0) g_done = 0u;

    const int wid  = threadIdx.x >> 5;
    const int lane = threadIdx.x & 31;
    const int row0 = blockIdx.x * 16 + wid * 2;
    const int row1 = row0 + 1;

    // 4 independent 128-bit loads in flight per thread
    const float4* s0 = (const float4*)(emb + (size_t)row0 * DD);
    const float4* s1 = (const float4*)(emb + (size_t)row1 * DD);
    float4 a0 = __ldg(&s0[lane * 2]);
    float4 b0 = __ldg(&s0[lane * 2 + 1]);
    float4 a1 = __ldg(&s1[lane * 2]);
    float4 b1 = __ldg(&s1[lane * 2 + 1]);

    float x0[8] = {a0.x, a0.y, a0.z, a0.w, b0.x, b0.y, b0.z, b0.w};
    float x1[8] = {a1.x, a1.y, a1.z, a1.w, b1.x, b1.y, b1.z, b1.w};

    alignas(16) __nv_bfloat16 h0[8], h1[8];
    float s0v = 0.f, m0v = 0.f, s1v = 0.f, m1v = 0.f;
    #pragma unroll
    for (int t = 0; t < 8; t++) {
        h0[t] = __float2bfloat16(x0[t]);
        h1[t] = __float2bfloat16(x1[t]);
        s0v += x0[t] * x0[t];  m0v += x0[t];
        s1v += x1[t] * x1[t];  m1v += x1[t];
    }
    *(uint4*)(g_panel + (size_t)row0 * 256 + lane * 8) = *(const uint4*)h0;
    *(uint4*)(g_panel + (size_t)row1 * 256 + lane * 8) = *(const uint4*)h1;

    #pragma unroll
    for (int off = 16; off; off >>= 1) {
        s0v += __shfl_xor_sync(0xffffffffu, s0v, off);
        m0v += __shfl_xor_sync(0xffffffffu, m0v, off);
        s1v += __shfl_xor_sync(0xffffffffu, s1v, off);
        m1v += __shfl_xor_sync(0xffffffffu, m1v, off);
    }
    if (lane == 0) {
        g_sq[row0]  = s0v;  g_sum[row0] = m0v;
        g_sq[row1]  = s1v;  g_sum[row1] = m1v;
        g_neg_pack[row0] = 0xffffffffffffffffull;
        g_neg_pack[row1] = 0xffffffffffffffffull;
        g_pos_pack[row0] = 0ull;
        g_pos_pack[row1] = 0ull;
    }
}

__device__ __forceinline__ u64 pack_min(float v, int j) {
    return ((u64)__float_as_uint(fmaxf(v, 0.f)) << 32) | (unsigned)j;
}
__device__ __forceinline__ u64 pack_max(float v, int j) {
    return ((u64)__float_as_uint(fmaxf(v, 0.f)) << 32) | (unsigned)(~j);
}

// ---------------- triangular GEMM (R10 config) + atomic epilogue + fused loss tail ----------------
__global__ __launch_bounds__(256, 2)
void gemm_kernel(float* __restrict__ out) {
    extern __shared__ char dsm[];
    __shared__ int s_last;
    const int tid = threadIdx.x;

    // decode blockIdx.x -> (ti, tj) with tj >= ti
    int rem = blockIdx.x, ti = 0;
    while (rem >= NTI - ti) { rem -= NTI - ti; ti++; }
    const int tj = ti + rem;

    const int i0 = ti * TI;
    const int j0 = tj * TJ;
    const int wid = tid >> 5, lane = tid & 31;
    const int wm  = wid >> 2, wn = wid & 3;   // 2 x 4 warp grid
    const bool diag = (ti == tj);

    const uint32_t sbase = (uint32_t)__cvta_generic_to_shared(dsm);
    float* s_sqi = (float*)(dsm + SQ_OFF);
    float* s_sqj = (float*)(dsm + SQ_OFF + 512);

    const char* gp = (const char*)g_panel;

    auto load_stage = [&](int kc, int s) {
        const uint32_t aBase = sbase + s * STAGE_BYTES;
        const uint32_t bBase = aBase + TI * 128;
        const int koff = kc * KC;
        #pragma unroll
        for (int it = 0; it < 4; it++) {
            const int idx = tid + 256 * it;
            const int row = idx >> 3, seg = idx & 7;
            const int off = row * 128 + seg * 16;
            cp16(aBase + (off ^ ((off >> 3) & 0x70)),
                 gp + ((size_t)(i0 + row) * 256 + koff + seg * 8) * 2);
        }
        #pragma unroll
        for (int it = 0; it < 4; it++) {
            const int idx = tid + 256 * it;
            const int row = idx >> 3, seg = idx & 7;
            const int off = row * 128 + seg * 16;
            cp16(bBase + (off ^ ((off >> 3) & 0x70)),
                 gp + ((size_t)(j0 + row) * 256 + koff + seg * 8) * 2);
        }
        CP_COMMIT();
    };

    // fill pipeline first, then blocking sq gathers
    load_stage(0, 0);
    load_stage(1, 1);

    if (tid < 128) s_sqi[tid] = g_sq[i0 + tid];
    else           s_sqj[tid - 128] = g_sq[j0 + tid - 128];

    float acc[4][4][4];
    #pragma unroll
    for (int a = 0; a < 4; a++)
        #pragma unroll
        for (int b = 0; b < 4; b++)
            #pragma unroll
            for (int c = 0; c < 4; c++) acc[a][b][c] = 0.f;

    #pragma unroll 1
    for (int kc = 0; kc < NCHUNK; kc++) {
        if (kc < NCHUNK - 1) { CP_WAIT(1); }
        else                 { CP_WAIT(0); }
        __syncthreads();   // stage kc visible to all; all warps done with kc-1

        if (kc + 2 < NCHUNK) load_stage(kc + 2, (kc + 2) % 3);

        const uint32_t aBase = sbase + (kc % 3) * STAGE_BYTES;
        const uint32_t bBase = aBase + TI * 128;

        #pragma unroll
        for (int ks = 0; ks < 4; ks++) {
            uint32_t afr[4][4];
            #pragma unroll
            for (int fm = 0; fm < 4; fm++) {
                const int row = wm * 64 + fm * 16 + (lane & 15);
                const int ch  = (ks * 2 + (lane >> 4)) ^ (row & 7);
                LDSM4(afr[fm], aBase + row * 128 + ch * 16);
            }
            uint32_t bfr[2][4];
            #pragma unroll
            for (int g = 0; g < 2; g++) {
                const int row = wn * 32 + g * 16 + (lane & 7) + ((lane >> 4) & 1) * 8;
                const int ch  = (ks * 2 + ((lane >> 3) & 1)) ^ (row & 7);
                LDSM4(bfr[g], bBase + row * 128 + ch * 16);
            }
            #pragma unroll
            for (int fm = 0; fm < 4; fm++)
                #pragma unroll
                for (int fn = 0; fn < 4; fn++)
                    MMA16816(acc[fm][fn], afr[fm], &bfr[fn >> 1][(fn & 1) * 2]);
        }
    }

    // ---- epilogue: packed atomics ----
    #pragma unroll
    for (int fm = 0; fm < 4; fm++) {
        #pragma unroll
        for (int h = 0; h < 2; h++) {
            const int rl = wm * 64 + fm * 16 + h * 8 + (lane >> 2);
            const int i  = i0 + rl;
            const int ci = i >> 4;
            const float sqi = s_sqi[rl];

            float bnv = 3.0e38f;  int bnj = 0x7fffffff;
            float bpv = -3.0e38f; int bpj = 0;

            #pragma unroll
            for (int fn = 0; fn < 4; fn++) {
                #pragma unroll
                for (int e = 0; e < 2; e++) {
                    const int cl = wn * 32 + fn * 8 + (lane & 3) * 2 + e;
                    const int j  = j0 + cl;
                    const float d2 = sqi + s_sqj[cl] - 2.f * acc[fm][fn][h * 2 + e];
                    if (diag && ((j >> 4) == ci)) {
                        if (d2 > bpv) { bpv = d2; bpj = j; }
                    } else {
                        if (d2 < bnv) { bnv = d2; bnj = j; }
                    }
                }
            }
            #pragma unroll
            for (int m = 1; m <= 2; m <<= 1) {
                float ov; int oj;
                ov = __shfl_xor_sync(0xffffffffu, bnv, m);
                oj = __shfl_xor_sync(0xffffffffu, bnj, m);
                if (ov < bnv || (ov == bnv && oj < bnj)) { bnv = ov; bnj = oj; }
                ov = __shfl_xor_sync(0xffffffffu, bpv, m);
                oj = __shfl_xor_sync(0xffffffffu, bpj, m);
                if (ov > bpv || (ov == bpv && oj < bpj)) { bpv = ov; bpj = oj; }
            }
            if ((lane & 3) == 0) {
                atomicMin(&g_neg_pack[i], pack_min(bnv, bnj));
                if (diag) atomicMax(&g_pos_pack[i], pack_max(bpv, bpj));
            }
        }
    }

    if (!diag) {
        #pragma unroll
        for (int fn = 0; fn < 4; fn++) {
            #pragma unroll
            for (int e = 0; e < 2; e++) {
                const int cl = wn * 32 + fn * 8 + (lane & 3) * 2 + e;
                const float sqj = s_sqj[cl];
                float bv = 3.0e38f; int bi = 0x7fffffff;
                #pragma unroll
                for (int fm = 0; fm < 4; fm++) {
                    #pragma unroll
                    for (int h = 0; h < 2; h++) {
                        const int rl = wm * 64 + fm * 16 + h * 8 + (lane >> 2);
                        const float d2 = s_sqi[rl] + sqj - 2.f * acc[fm][fn][h * 2 + e];
                        if (d2 < bv) { bv = d2; bi = i0 + rl; }
                    }
                }
                #pragma unroll
                for (int m = 4; m <= 16; m <<= 1) {
                    const float ov = __shfl_xor_sync(0xffffffffu, bv, m);
                    const int   oi = __shfl_xor_sync(0xffffffffu, bi, m);
                    if (ov < bv || (ov == bv && oi < bi)) { bv = ov; bi = oi; }
                }
                if ((lane >> 2) == 0)
                    atomicMin(&g_neg_pack[j0 + cl], pack_min(bv, bi));
            }
        }
    }

    // ---- fused finalize: the last CTA to finish computes the loss ----
    __threadfence();
    __syncthreads();
    if (tid == 0) s_last = (atomicAdd(&g_done, 1u) == NTILES - 1) ? 1 : 0;
    __syncthreads();

    if (s_last) {
        __threadfence();
        float* sh = (float*)dsm;
        const float eterm = (float)DD * EPSF * EPSF;
        float lsum = 0.f;
        #pragma unroll
        for (int r = 0; r < NN / 256; r++) {
            const int i = r * 256 + tid;
            const u64 np = g_neg_pack[i];
            const u64 pp = g_pos_pack[i];
            const int n = (int)(unsigned)(np & 0xffffffffull);
            const int p = (int)~(unsigned)(pp & 0xffffffffull);
            const float d2n = __uint_as_float((unsigned)(np >> 32));
            const float d2p = __uint_as_float((unsigned)(pp >> 32));
            const float Si = g_sum[i];
            const float ap2 = d2p + 2.f * EPSF * (Si - g_sum[p]) + eterm;
            const float an2 = d2n + 2.f * EPSF * (Si - g_sum[n]) + eterm;
            lsum += fmaxf(sqrtf(fmaxf(ap2, 0.f)) - sqrtf(fmaxf(an2, 0.f)) + MARGINF, 0.f);
        }
        sh[tid] = lsum;
        __syncthreads();
        for (int off = 128; off; off >>= 1) {
            if (tid < off) sh[tid] += sh[tid + off];
            __syncthreads();
        }
        if (tid == 0) out[0] = sh[0] * (1.0f / (float)NN);
    }
}

extern "C" void kernel_launch(void* const* d_in, const int* in_sizes, int n_in,
                              void* d_out, int out_size) {
    const float* emb = (const float*)d_in[0];
    float* out = (float*)d_out;

    static bool attr_set = false;
    if (!attr_set) {
        cudaFuncSetAttribute(gemm_kernel, cudaFuncAttributeMaxDynamicSharedMemorySize, DYN_SMEM);
        attr_set = true;
    }

    prep_kernel<<<NN / 16, 256>>>(emb);
    gemm_kernel<<<NTILES, 256, DYN_SMEM>>>(out);
}

// round 14
// speedup vs baseline: 2.1251x; 1.4643x over previous
#include <cuda_runtime.h>
#include <cuda_bf16.h>
#include <cstdint>

#define NC 256
#define KK 16
#define DD 256
#define NN 4096
#define MARGINF 1.0f
#define EPSF 1e-6f

#define TI 128
#define TJ 128
#define KC 64            // bf16 per k-chunk (128B rows)
#define NCHUNK 4         // K = 256 (hi-only)
#define NTI (NN / TI)    // 32
#define NTILES (NTI * (NTI + 1) / 2)   // 528

#define STAGE_BYTES (TI*128 + TJ*128)   // 32 KB
#define SQ_OFF      (3 * STAGE_BYTES)   // 96 KB
#define DYN_SMEM    (SQ_OFF + 1024)

typedef unsigned long long u64;

__device__ __nv_bfloat16 g_panel[(size_t)NN * 256];   // hi only
__device__ float g_sq[NN];
__device__ float g_sum[NN];         // row sums (for eps correction)
__device__ u64   g_neg_pack[NN];    // (d2_bits<<32)|j   : atomicMin
__device__ u64   g_pos_pack[NN];    // (d2_bits<<32)|~j  : atomicMax
__device__ u64   g_sum_fix;
__device__ unsigned int g_done;

#define FIX_SCALE 17592186044416.0   // 2^44

#define LDSM4(r, a) \
    asm volatile("ldmatrix.sync.aligned.m8n8.x4.shared.b16 {%0,%1,%2,%3}, [%4];" \
        : "=r"((r)[0]), "=r"((r)[1]), "=r"((r)[2]), "=r"((r)[3]) : "r"(a))

#define MMA16816(c, a, b) \
    asm volatile("mma.sync.aligned.m16n8k16.row.col.f32.bf16.bf16.f32 " \
        "{%0,%1,%2,%3}, {%4,%5,%6,%7}, {%8,%9}, {%0,%1,%2,%3};" \
        : "+f"((c)[0]), "+f"((c)[1]), "+f"((c)[2]), "+f"((c)[3]) \
        : "r"((a)[0]), "r"((a)[1]), "r"((a)[2]), "r"((a)[3]), \
          "r"((b)[0]), "r"((b)[1]))

__device__ __forceinline__ void cp16(uint32_t dst, const void* src) {
    asm volatile("cp.async.cg.shared.global [%0], [%1], 16;" :: "r"(dst), "l"(src));
}
#define CP_COMMIT() asm volatile("cp.async.commit_group;")
#define CP_WAIT(n)  asm volatile("cp.async.wait_group %0;" :: "n"(n))

// ---------------- prep: fp32 -> bf16 hi panel + sq + sum + init ----------------
__global__ __launch_bounds__(256) void prep_kernel(const float* __restrict__ emb) {
    if (blockIdx.x == 0 && threadIdx.x == 0) { g_sum_fix = 0ull; g_done = 0u; }

    const int row  = blockIdx.x * 8 + (threadIdx.x >> 5);
    const int lane = threadIdx.x & 31;

    const float4* src = (const float4*)(emb + (size_t)row * DD);
    float4 a = __ldg(&src[lane * 2]);
    float4 b = __ldg(&src[lane * 2 + 1]);
    float x[8] = {a.x, a.y, a.z, a.w, b.x, b.y, b.z, b.w};

    alignas(16) __nv_bfloat16 hi[8];
    float s = 0.f, m = 0.f;
    #pragma unroll
    for (int t = 0; t < 8; t++) {
        hi[t] = __float2bfloat16(x[t]);
        s += x[t] * x[t];
        m += x[t];
    }
    *(uint4*)(g_panel + (size_t)row * 256 + lane * 8) = *(const uint4*)hi;

    #pragma unroll
    for (int off = 16; off; off >>= 1) {
        s += __shfl_xor_sync(0xffffffffu, s, off);
        m += __shfl_xor_sync(0xffffffffu, m, off);
    }
    if (lane == 0) {
        g_sq[row]  = s;
        g_sum[row] = m;
        g_neg_pack[row] = 0xffffffffffffffffull;
        g_pos_pack[row] = 0ull;
    }
}

__device__ __forceinline__ u64 pack_min(float v, int j) {
    return ((u64)__float_as_uint(fmaxf(v, 0.f)) << 32) | (unsigned)j;
}
__device__ __forceinline__ u64 pack_max(float v, int j) {
    return ((u64)__float_as_uint(fmaxf(v, 0.f)) << 32) | (unsigned)(~j);
}

// ---------------- triangular GEMM (hoisted addressing) + atomic epilogue ----------------
__global__ __launch_bounds__(256, 2)
void gemm_kernel() {
    extern __shared__ char dsm[];
    const int tid = threadIdx.x;

    // decode blockIdx.x -> (ti, tj) with tj >= ti
    int rem = blockIdx.x, ti = 0;
    while (rem >= NTI - ti) { rem -= NTI - ti; ti++; }
    const int tj = ti + rem;

    const int i0 = ti * TI;
    const int j0 = tj * TJ;
    const int wid = tid >> 5, lane = tid & 31;
    const int wm  = wid >> 2, wn = wid & 3;   // 2 x 4 warp grid
    const bool diag = (ti == tj);

    const uint32_t sbase = (uint32_t)__cvta_generic_to_shared(dsm);
    float* s_sqi = (float*)(dsm + SQ_OFF);
    float* s_sqj = (float*)(dsm + SQ_OFF + 512);

    const char* gp = (const char*)g_panel;

    // ---- hoisted cp.async addressing (kc-invariant) ----
    const char* srcA[4]; const char* srcB[4];
    uint32_t dstA[4], dstB[4];
    #pragma unroll
    for (int it = 0; it < 4; it++) {
        const int idx = tid + 256 * it;
        const int row = idx >> 3, seg = idx & 7;
        srcA[it] = gp + (size_t)(i0 + row) * 512 + seg * 16;
        srcB[it] = gp + (size_t)(j0 + row) * 512 + seg * 16;
        const uint32_t off = row * 128 + seg * 16;
        dstA[it] = off ^ ((off >> 3) & 0x70);
        dstB[it] = dstA[it] + TI * 128;
    }

    auto load_stage = [&](int kc, int s) {
        const uint32_t base = sbase + s * STAGE_BYTES;
        const int kb = kc * 128;   // bytes of k offset
        #pragma unroll
        for (int it = 0; it < 4; it++) cp16(base + dstA[it], srcA[it] + kb);
        #pragma unroll
        for (int it = 0; it < 4; it++) cp16(base + dstB[it], srcB[it] + kb);
        CP_COMMIT();
    };

    // ---- hoisted ldmatrix relative addresses (XOR-foldable in ks) ----
    uint32_t aRel[4], bRel[2];
    #pragma unroll
    for (int fm = 0; fm < 4; fm++) {
        const int row = wm * 64 + fm * 16 + (lane & 15);
        aRel[fm] = row * 128 + (((lane >> 4) ^ (row & 7)) * 16);
    }
    #pragma unroll
    for (int g = 0; g < 2; g++) {
        const int row = wn * 32 + g * 16 + (lane & 7) + ((lane >> 4) & 1) * 8;
        bRel[g] = TI * 128 + row * 128 + ((((lane >> 3) & 1) ^ (row & 7)) * 16);
    }

    // fill pipeline first, then blocking sq gathers
    load_stage(0, 0);
    load_stage(1, 1);

    if (tid < 128) s_sqi[tid] = g_sq[i0 + tid];
    else           s_sqj[tid - 128] = g_sq[j0 + tid - 128];

    float acc[4][4][4];
    #pragma unroll
    for (int a = 0; a < 4; a++)
        #pragma unroll
        for (int b = 0; b < 4; b++)
            #pragma unroll
            for (int c = 0; c < 4; c++) acc[a][b][c] = 0.f;

    #pragma unroll 1
    for (int kc = 0; kc < NCHUNK; kc++) {
        if (kc < NCHUNK - 1) { CP_WAIT(1); }
        else                 { CP_WAIT(0); }
        __syncthreads();   // stage kc visible to all; all warps done with kc-1

        if (kc + 2 < NCHUNK) load_stage(kc + 2, (kc + 2) % 3);

        const uint32_t sBase = sbase + (kc % 3) * STAGE_BYTES;

        #pragma unroll
        for (int ks = 0; ks < 4; ks++) {
            const uint32_t kx = ks * 32;
            uint32_t afr[4][4];
            #pragma unroll
            for (int fm = 0; fm < 4; fm++)
                LDSM4(afr[fm], sBase + (aRel[fm] ^ kx));
            uint32_t bfr[2][4];
            #pragma unroll
            for (int g = 0; g < 2; g++)
                LDSM4(bfr[g], sBase + (bRel[g] ^ kx));
            #pragma unroll
            for (int fm = 0; fm < 4; fm++)
                #pragma unroll
                for (int fn = 0; fn < 4; fn++)
                    MMA16816(acc[fm][fn], afr[fm], &bfr[fn >> 1][(fn & 1) * 2]);
        }
    }

    // ---- epilogue: packed atomics ----
    #pragma unroll
    for (int fm = 0; fm < 4; fm++) {
        #pragma unroll
        for (int h = 0; h < 2; h++) {
            const int rl = wm * 64 + fm * 16 + h * 8 + (lane >> 2);
            const int i  = i0 + rl;
            const int ci = i >> 4;
            const float sqi = s_sqi[rl];

            float bnv = 3.0e38f;  int bnj = 0x7fffffff;
            float bpv = -3.0e38f; int bpj = 0;

            #pragma unroll
            for (int fn = 0; fn < 4; fn++) {
                #pragma unroll
                for (int e = 0; e < 2; e++) {
                    const int cl = wn * 32 + fn * 8 + (lane & 3) * 2 + e;
                    const int j  = j0 + cl;
                    const float d2 = sqi + s_sqj[cl] - 2.f * acc[fm][fn][h * 2 + e];
                    if (diag && ((j >> 4) == ci)) {
                        if (d2 > bpv) { bpv = d2; bpj = j; }
                    } else {
                        if (d2 < bnv) { bnv = d2; bnj = j; }
                    }
                }
            }
            #pragma unroll
            for (int m = 1; m <= 2; m <<= 1) {
                float ov; int oj;
                ov = __shfl_xor_sync(0xffffffffu, bnv, m);
                oj = __shfl_xor_sync(0xffffffffu, bnj, m);
                if (ov < bnv || (ov == bnv && oj < bnj)) { bnv = ov; bnj = oj; }
                ov = __shfl_xor_sync(0xffffffffu, bpv, m);
                oj = __shfl_xor_sync(0xffffffffu, bpj, m);
                if (ov > bpv || (ov == bpv && oj < bpj)) { bpv = ov; bpj = oj; }
            }
            if ((lane & 3) == 0) {
                atomicMin(&g_neg_pack[i], pack_min(bnv, bnj));
                if (diag) atomicMax(&g_pos_pack[i], pack_max(bpv, bpj));
            }
        }
    }

    if (!diag) {
        #pragma unroll
        for (int fn = 0; fn < 4; fn++) {
            #pragma unroll
            for (int e = 0; e < 2; e++) {
                const int cl = wn * 32 + fn * 8 + (lane & 3) * 2 + e;
                const float sqj = s_sqj[cl];
                float bv = 3.0e38f; int bi = 0x7fffffff;
                #pragma unroll
                for (int fm = 0; fm < 4; fm++) {
                    #pragma unroll
                    for (int h = 0; h < 2; h++) {
                        const int rl = wm * 64 + fm * 16 + h * 8 + (lane >> 2);
                        const float d2 = s_sqi[rl] + sqj - 2.f * acc[fm][fn][h * 2 + e];
                        if (d2 < bv) { bv = d2; bi = i0 + rl; }
                    }
                }
                #pragma unroll
                for (int m = 4; m <= 16; m <<= 1) {
                    const float ov = __shfl_xor_sync(0xffffffffu, bv, m);
                    const int   oi = __shfl_xor_sync(0xffffffffu, bi, m);
                    if (ov < bv || (ov == bv && oi < bi)) { bv = ov; bi = oi; }
                }
                if ((lane >> 2) == 0)
                    atomicMin(&g_neg_pack[j0 + cl], pack_min(bv, bi));
            }
        }
    }
}

// ---------------- finalize: algebraic loss from packs ----------------
#define LB 16
__global__ __launch_bounds__(256) void loss_kernel(float* __restrict__ out) {
    const int i = blockIdx.x * 256 + threadIdx.x;
    __shared__ float sh[256];

    const u64 np = g_neg_pack[i];
    const u64 pp = g_pos_pack[i];
    const int n = (int)(unsigned)(np & 0xffffffffull);
    const int p = (int)~(unsigned)(pp & 0xffffffffull);
    const float d2n = __uint_as_float((unsigned)(np >> 32));
    const float d2p = __uint_as_float((unsigned)(pp >> 32));

    const float Si = g_sum[i];
    const float eterm = (float)DD * EPSF * EPSF;

    const float ap2 = d2p + 2.f * EPSF * (Si - g_sum[p]) + eterm;
    const float an2 = d2n + 2.f * EPSF * (Si - g_sum[n]) + eterm;
    const float d_ap = sqrtf(fmaxf(ap2, 0.f));
    const float d_an = sqrtf(fmaxf(an2, 0.f));

    sh[threadIdx.x] = fmaxf(d_ap - d_an + MARGINF, 0.f);
    __syncthreads();

    for (int off = 128; off; off >>= 1) {
        if (threadIdx.x < off) sh[threadIdx.x] += sh[threadIdx.x + off];
        __syncthreads();
    }

    if (threadIdx.x == 0) {
        const u64 fx = (u64)((double)sh[0] * FIX_SCALE + 0.5);
        atomicAdd(&g_sum_fix, fx);
        __threadfence();
        const unsigned done = atomicAdd(&g_done, 1u);
        if (done == LB - 1) {
            const u64 tot = atomicAdd(&g_sum_fix, 0ull);
            out[0] = (float)((double)tot / FIX_SCALE / (double)NN);
        }
    }
}

extern "C" void kernel_launch(void* const* d_in, const int* in_sizes, int n_in,
                              void* d_out, int out_size) {
    const float* emb = (const float*)d_in[0];
    float* out = (float*)d_out;

    static bool attr_set = false;
    if (!attr_set) {
        cudaFuncSetAttribute(gemm_kernel, cudaFuncAttributeMaxDynamicSharedMemorySize, DYN_SMEM);
        attr_set = true;
    }

    prep_kernel<<<NN / 8, 256>>>(emb);
    gemm_kernel<<<NTILES, 256, DYN_SMEM>>>();
    loss_kernel<<<LB, 256>>>(out);
}